// round 15
// baseline (speedup 1.0000x reference)
#include <cuda_runtime.h>
#include <cuda_fp16.h>
#include <math.h>
#include <stdint.h>

#define BB 256
#define TT 32
#define SS 128
#define II 256
#define HH 1024
#define OO 256
#define G4 4096

// ---------------- scratch (static device globals; no allocation) ------------
__device__ uint32_t d_Xg16[(size_t)TT * BB * 2048]; // input gates + biases, fp16 pairs
__device__ float d_h[4][BB * HH];                // ring-buffered hidden (fp32)
__device__ uint32_t d_h16[4][BB * 512];          // hidden, f16x2 words, frag-permuted
__device__ float d_c[BB * HH];
__device__ uint32_t d_u16[4][BB * 1024];         // [ctx|h] f16x2 words, permuted (ring 4)
__device__ float d_fcp[4][4][BB * OO];           // split-K FC partials (ring 4)
__device__ uint32_t d_Wih16[G4 * 128];           // fp16 pairs, word-permuted
__device__ uint32_t d_Whh16[(size_t)G4 * 512];
__device__ uint32_t d_Wfc16[OO * 1024];
__device__ uint32_t d_st16[8192 * 128];          // shifted_target fp16, m-major (t*256+b)

// ---------------- helpers ----------------------------------------------------
__device__ __forceinline__ uint32_t packf16(float a, float b) {
    __half2 h = __floats2half2_rn(a, b);
    return *reinterpret_cast<uint32_t*>(&h);
}
__device__ __forceinline__ uint32_t cvta_s(const void* p) {
    return (uint32_t)__cvta_generic_to_shared(p);
}
// permute word index within its 8-word group so (w, w+4) become adjacent
__device__ __forceinline__ int kperm(int k) {
    return (k & ~7) + ((k & 3) << 1) + ((k >> 2) & 1);
}
#define CPASYNC16(sa, g) asm volatile("cp.async.cg.shared.global [%0], [%1], 16;" :: "r"(sa), "l"(g))
#define CPCOMMIT() asm volatile("cp.async.commit_group;")
#define CPWAIT(n) asm volatile("cp.async.wait_group %0;" :: "n"(n))

__device__ __forceinline__ void mma_f16(float c[4], const uint32_t a[4], const uint32_t b[2]) {
    asm volatile(
        "mma.sync.aligned.m16n8k16.row.col.f32.f16.f16.f32 "
        "{%0,%1,%2,%3}, {%4,%5,%6,%7}, {%8,%9}, {%0,%1,%2,%3};"
        : "+f"(c[0]), "+f"(c[1]), "+f"(c[2]), "+f"(c[3])
        : "r"(a[0]), "r"(a[1]), "r"(a[2]), "r"(a[3]), "r"(b[0]), "r"(b[1]));
}

#define SIG(x) (1.f / (1.f + __expf(-(x))))

// ========== precompute GEMM (k_pre): 128x128 tiles, fp16, depth-2 ============
__device__ __forceinline__ void gemm_pre(
    int ctam, int ctan,
    const float* __restrict__ e1, const float* __restrict__ e2,
    uint32_t* __restrict__ XgO, char* dyn)
{
    uint32_t* As = (uint32_t*)dyn;
    uint32_t* Bs = (uint32_t*)(dyn + 40960);
    const int tid = threadIdx.x;
    const int lane = tid & 31;
    const int wid = tid >> 5;
    const int wm = wid & 3;
    const int wn = wid >> 2;
    const int tg = lane & 3;
    const int gpr = lane >> 2;

    float acc[2][8][4];
#pragma unroll
    for (int i = 0; i < 2; ++i)
#pragma unroll
        for (int j = 0; j < 8; ++j)
#pragma unroll
            for (int k = 0; k < 4; ++k) acc[i][j][k] = 0.f;

    auto stage = [&](int buf, int kcw) {
#pragma unroll
        for (int it = 0; it < 4; ++it) {
            int slot = it * 256 + tid;
            int row = slot >> 3;
            int cc = (slot & 7) << 2;
            CPASYNC16(cvta_s(As + buf * 5120 + row * 40 + cc),
                      d_st16 + (size_t)(ctam * 128 + row) * 128 + kcw + cc);
        }
#pragma unroll
        for (int it = 0; it < 4; ++it) {
            int slot = it * 256 + tid;
            int row = slot >> 3;
            int cc = (slot & 7) << 2;
            CPASYNC16(cvta_s(Bs + buf * 5120 + row * 40 + cc),
                      d_Wih16 + (size_t)(ctan * 128 + row) * 128 + kcw + cc);
        }
    };

    stage(0, 0);
    CPCOMMIT();
    const int nc = 4;
    for (int c = 0; c < nc; ++c) {
        if (c + 1 < nc) { stage((c + 1) & 1, (c + 1) * 32); CPCOMMIT(); CPWAIT(1); }
        else CPWAIT(0);
        __syncthreads();
        const uint32_t* Af = As + (c & 1) * 5120;
        const uint32_t* Bf = Bs + (c & 1) * 5120;
#pragma unroll
        for (int ks = 0; ks < 4; ++ks) {
            uint32_t a[2][4], b[8][2];
#pragma unroll
            for (int mt = 0; mt < 2; ++mt) {
                int r = wm * 32 + mt * 16 + gpr;
                uint2 lo = *(const uint2*)(Af + r * 40 + ks * 8 + tg * 2);
                uint2 hi = *(const uint2*)(Af + (r + 8) * 40 + ks * 8 + tg * 2);
                a[mt][0] = lo.x; a[mt][2] = lo.y;
                a[mt][1] = hi.x; a[mt][3] = hi.y;
            }
#pragma unroll
            for (int nt = 0; nt < 8; ++nt) {
                int n = wn * 64 + nt * 8 + gpr;
                uint2 v = *(const uint2*)(Bf + n * 40 + ks * 8 + tg * 2);
                b[nt][0] = v.x; b[nt][1] = v.y;
            }
#pragma unroll
            for (int mt = 0; mt < 2; ++mt)
#pragma unroll
                for (int nt = 0; nt < 8; ++nt)
                    mma_f16(acc[mt][nt], a[mt], b[nt]);
        }
        __syncthreads();
    }
#pragma unroll
    for (int mt = 0; mt < 2; ++mt)
#pragma unroll
        for (int nt = 0; nt < 8; ++nt) {
            int gm0 = ctam * 128 + wm * 32 + mt * 16 + gpr;
            int gn = ctan * 128 + wn * 64 + nt * 8 + tg * 2;
#pragma unroll
            for (int half = 0; half < 2; ++half) {
                int gm = gm0 + half * 8;
                float v0 = acc[mt][nt][half * 2 + 0] + e1[gn] + e2[gn];
                float v1 = acc[mt][nt][half * 2 + 1] + e1[gn + 1] + e2[gn + 1];
                XgO[(size_t)gm * 2048 + (gn >> 1)] = packf16(v0, v1);
            }
        }
}

// ========== fused gates GEMM + LSTM cell (fp16 fragments) =====================
// 128 CTAs = ctam(4) x ctan(32). CTA 64M x 128N (4 gates x 32 cols).
__device__ __forceinline__ void gatescell_dev(
    int ctam, int ctan,
    const uint32_t* __restrict__ hA,   // h_{t-1}, f16x2 permuted
    const uint32_t* __restrict__ Xg16, // d_Xg16 + t*BB*2048
    float* __restrict__ hOut,
    uint32_t* __restrict__ hOut16,
    char* dyn)
{
    uint32_t* As = (uint32_t*)dyn;
    uint32_t* Bs = (uint32_t*)(dyn + 30720);
    const int tid = threadIdx.x;
    const int lane = tid & 31;
    const int wid = tid >> 5;
    const int wm = wid & 1;
    const int g = wid >> 1;
    const int tg = lane & 3;
    const int gpr = lane >> 2;
    const int q0 = ctan * 32;
    const int m0 = ctam * 64;

    float acc[2][4][4];
#pragma unroll
    for (int i = 0; i < 2; ++i)
#pragma unroll
        for (int j = 0; j < 4; ++j)
#pragma unroll
            for (int k = 0; k < 4; ++k) acc[i][j][k] = 0.f;

    auto stage = [&](int buf, int kcw) {
#pragma unroll
        for (int it = 0; it < 2; ++it) {
            int slot = it * 256 + tid;
            int row = slot >> 3;
            int cc = (slot & 7) << 2;
            CPASYNC16(cvta_s(As + buf * 2560 + row * 40 + cc),
                      hA + (size_t)(m0 + row) * 512 + kcw + cc);
        }
#pragma unroll
        for (int it = 0; it < 4; ++it) {
            int slot = it * 256 + tid;
            int row = slot >> 3;
            int cc = (slot & 7) << 2;
            int wr = (row >> 5) * HH + q0 + (row & 31);
            CPASYNC16(cvta_s(Bs + buf * 5120 + row * 40 + cc),
                      d_Whh16 + (size_t)wr * 512 + kcw + cc);
        }
    };

    stage(0, 0); CPCOMMIT();
    stage(1, 32); CPCOMMIT();
    const int nc = 16;
    for (int c = 0; c < nc; ++c) {
        if (c + 2 < nc) { stage((c + 2) % 3, (c + 2) * 32); CPCOMMIT(); CPWAIT(2); }
        else if (c + 1 < nc) { CPWAIT(1); }
        else { CPWAIT(0); }
        __syncthreads();
        const uint32_t* Af = As + (c % 3) * 2560;
        const uint32_t* Bf = Bs + (c % 3) * 5120;
#pragma unroll
        for (int ks = 0; ks < 4; ++ks) {
            uint32_t a[2][4], b[4][2];
#pragma unroll
            for (int mt = 0; mt < 2; ++mt) {
                int r = wm * 32 + mt * 16 + gpr;
                uint2 lo = *(const uint2*)(Af + r * 40 + ks * 8 + tg * 2);
                uint2 hi = *(const uint2*)(Af + (r + 8) * 40 + ks * 8 + tg * 2);
                a[mt][0] = lo.x; a[mt][2] = lo.y;
                a[mt][1] = hi.x; a[mt][3] = hi.y;
            }
#pragma unroll
            for (int nt = 0; nt < 4; ++nt) {
                int n = g * 32 + nt * 8 + gpr;
                uint2 v = *(const uint2*)(Bf + n * 40 + ks * 8 + tg * 2);
                b[nt][0] = v.x; b[nt][1] = v.y;
            }
#pragma unroll
            for (int mt = 0; mt < 2; ++mt)
#pragma unroll
                for (int nt = 0; nt < 4; ++nt)
                    mma_f16(acc[mt][nt], a[mt], b[nt]);
        }
        __syncthreads();
    }

    // gate exchange: ep[row 64][n 128], stride 132
    float* ep = (float*)dyn;
    __syncthreads();
#pragma unroll
    for (int mt = 0; mt < 2; ++mt)
#pragma unroll
        for (int nt = 0; nt < 4; ++nt) {
            int r0 = wm * 32 + mt * 16 + gpr;
            int col = g * 32 + nt * 8 + tg * 2;
            *(float2*)(ep + r0 * 132 + col) = make_float2(acc[mt][nt][0], acc[mt][nt][1]);
            *(float2*)(ep + (r0 + 8) * 132 + col) = make_float2(acc[mt][nt][2], acc[mt][nt][3]);
        }
    __syncthreads();

#pragma unroll
    for (int k = 0; k < 4; ++k) {
        int idx = k * 256 + tid;
        int row = idx >> 4;
        int wq = idx & 15;
        int b = m0 + row;
        int q = q0 + wq * 2;
        const uint32_t* Xw = Xg16 + (size_t)b * 2048 + (q >> 1);
        float2 xi = __half22float2(*(const __half2*)&Xw[0]);
        float2 xf = __half22float2(*(const __half2*)&Xw[512]);
        float2 xg = __half22float2(*(const __half2*)&Xw[1024]);
        float2 xo = __half22float2(*(const __half2*)&Xw[1536]);
        int qq = wq * 2;
        float2 ei = *(const float2*)(ep + row * 132 + qq);
        float2 ef = *(const float2*)(ep + row * 132 + 32 + qq);
        float2 eg = *(const float2*)(ep + row * 132 + 64 + qq);
        float2 eo = *(const float2*)(ep + row * 132 + 96 + qq);
        size_t hb = (size_t)b * HH + q;
        float2 c2 = *(const float2*)(d_c + hb);
        c2.x = SIG(ef.x + xf.x) * c2.x + SIG(ei.x + xi.x) * tanhf(eg.x + xg.x);
        c2.y = SIG(ef.y + xf.y) * c2.y + SIG(ei.y + xi.y) * tanhf(eg.y + xg.y);
        float h0 = SIG(eo.x + xo.x) * tanhf(c2.x);
        float h1 = SIG(eo.y + xo.y) * tanhf(c2.y);
        *(float2*)(d_c + hb) = c2;
        *(float2*)(hOut + hb) = make_float2(h0, h1);
        hOut16[(size_t)b * 512 + kperm((q0 >> 1) + wq)] = packf16(h0, h1);
    }
}

// ========== FC split-K partial GEMM (fp16) ====================================
__device__ __forceinline__ void fcpart_dev(
    int ctam, int ctan, int kslice,
    const uint32_t* __restrict__ u16, float* __restrict__ part)
{
    extern __shared__ char dyn[];
    uint32_t* Af = (uint32_t*)dyn;
    uint32_t* Bf = (uint32_t*)(dyn + 61440);
    const int tid = threadIdx.x;
    const int lane = tid & 31;
    const int wid = tid >> 5;
    const int wm = wid & 3;
    const int wn = wid >> 2;
    const int tg = lane & 3;
    const int gpr = lane >> 2;
    const int k0w = kslice * 256;

    float acc[2][4][4];
#pragma unroll
    for (int i = 0; i < 2; ++i)
#pragma unroll
        for (int j = 0; j < 4; ++j)
#pragma unroll
            for (int k = 0; k < 4; ++k) acc[i][j][k] = 0.f;

    auto stage = [&](int buf, int kcw) {
#pragma unroll
        for (int it = 0; it < 4; ++it) {
            int slot = it * 256 + tid;
            int row = slot >> 3;
            int cc = (slot & 7) << 2;
            CPASYNC16(cvta_s(Af + buf * 5120 + row * 40 + cc),
                      u16 + (size_t)(ctam * 128 + row) * 1024 + k0w + kcw + cc);
        }
#pragma unroll
        for (int it = 0; it < 2; ++it) {
            int slot = it * 256 + tid;
            int row = slot >> 3;
            int cc = (slot & 7) << 2;
            CPASYNC16(cvta_s(Bf + buf * 2560 + row * 40 + cc),
                      d_Wfc16 + (size_t)(ctan * 64 + row) * 1024 + k0w + kcw + cc);
        }
    };

    stage(0, 0); CPCOMMIT();
    stage(1, 32); CPCOMMIT();
    const int nc = 8;
    for (int c = 0; c < nc; ++c) {
        if (c + 2 < nc) { stage((c + 2) % 3, (c + 2) * 32); CPCOMMIT(); CPWAIT(2); }
        else if (c + 1 < nc) { CPWAIT(1); }
        else { CPWAIT(0); }
        __syncthreads();
        const uint32_t* A = Af + (c % 3) * 5120;
        const uint32_t* B = Bf + (c % 3) * 2560;
#pragma unroll
        for (int ks = 0; ks < 4; ++ks) {
            uint32_t a[2][4], b[4][2];
#pragma unroll
            for (int mt = 0; mt < 2; ++mt) {
                int r = wm * 32 + mt * 16 + gpr;
                uint2 lo = *(const uint2*)(A + r * 40 + ks * 8 + tg * 2);
                uint2 hi = *(const uint2*)(A + (r + 8) * 40 + ks * 8 + tg * 2);
                a[mt][0] = lo.x; a[mt][2] = lo.y;
                a[mt][1] = hi.x; a[mt][3] = hi.y;
            }
#pragma unroll
            for (int nt = 0; nt < 4; ++nt) {
                int n = wn * 32 + nt * 8 + gpr;
                uint2 v = *(const uint2*)(B + n * 40 + ks * 8 + tg * 2);
                b[nt][0] = v.x; b[nt][1] = v.y;
            }
#pragma unroll
            for (int mt = 0; mt < 2; ++mt)
#pragma unroll
                for (int nt = 0; nt < 4; ++nt)
                    mma_f16(acc[mt][nt], a[mt], b[nt]);
        }
        __syncthreads();
    }
#pragma unroll
    for (int mt = 0; mt < 2; ++mt)
#pragma unroll
        for (int nt = 0; nt < 4; ++nt) {
            int gm0 = ctam * 128 + wm * 32 + mt * 16 + gpr;
            int gn = ctan * 64 + wn * 32 + nt * 8 + tg * 2;
            *(float2*)(part + (size_t)gm0 * OO + gn) =
                make_float2(acc[mt][nt][0], acc[mt][nt][1]);
            *(float2*)(part + (size_t)(gm0 + 8) * OO + gn) =
                make_float2(acc[mt][nt][2], acc[mt][nt][3]);
        }
}

// ========== two-step fused attention (register-cached e) ======================
// One CTA = one batch, TWO timesteps. enc[b] staged into smem ONCE (3-stage
// ring of 4 rows x 4KB). Warps 0-3 run step t-1, warps 4-7 run step t-2.
// Each row's 32 enc values are loaded into registers once and reused for
// both the dot and the ctx update -> halves LDS bytes.
__device__ __forceinline__ void attn2_dev(
    int b, int t, const float* __restrict__ enc, float* __restrict__ out,
    char* dyn, float s_sc[2][SS], float s_m2[2][4], float s_l2[2][4])
{
    float* es = (float*)dyn;               // 3 stages x 4096 floats (48 KB)
    const int tid = threadIdx.x;
    const int lane = tid & 31;
    const int w = tid >> 5;                // 0..7
    const int grp = w >> 2;                // 0 -> step t-1, 1 -> step t-2
    const int wr4 = w & 3;                 // row-within-stage
    const int s = t - 1 - grp;

    const float* hb = d_h[s & 3] + (size_t)b * HH;
    float hreg[32];
#pragma unroll
    for (int i = 0; i < 32; ++i) hreg[i] = hb[i * 32 + lane];

    const float* encb = enc + (size_t)b * SS * HH;

    auto stage = [&](int c) {
        const float* src = encb + (size_t)(c * 4) * HH;
        float* dst = es + (c % 3) * 4096;
#pragma unroll
        for (int it = 0; it < 4; ++it) {
            int slot = it * 256 + tid;
            CPASYNC16(cvta_s(dst + slot * 4), src + slot * 4);
        }
        CPCOMMIT();
    };
    stage(0); stage(1); stage(2);

    float m = -1e30f, l = 0.f;
    float ctx[32];
#pragma unroll
    for (int i = 0; i < 32; ++i) ctx[i] = 0.f;

    for (int c = 0; c < 32; ++c) {
        if (c < 30) { CPWAIT(2); }
        else if (c == 30) { CPWAIT(1); }
        else { CPWAIT(0); }
        __syncthreads();
        const float* e = es + (c % 3) * 4096 + wr4 * 1024;
        float er[32];
        float dot = 0.f;
#pragma unroll
        for (int i = 0; i < 32; ++i) {
            er[i] = e[i * 32 + lane];
            dot += hreg[i] * er[i];
        }
#pragma unroll
        for (int o = 16; o; o >>= 1) dot += __shfl_xor_sync(0xffffffffu, dot, o);
        int r = c * 4 + wr4;
        if (lane == 0) s_sc[grp][r] = dot;

        float nm = fmaxf(m, dot);
        float al = __expf(m - nm);
        float p = __expf(dot - nm);
        l = l * al + p;
#pragma unroll
        for (int i = 0; i < 32; ++i) ctx[i] = ctx[i] * al + p * er[i];
        m = nm;
        __syncthreads();                   // all warps done with buffer c%3
        if (c + 3 < 32) stage(c + 3);      // recycle it
    }

    if (lane == 0) { s_m2[grp][wr4] = m; s_l2[grp][wr4] = l; }
    __syncthreads();

    float M = -1e30f;
#pragma unroll
    for (int i = 0; i < 4; ++i) M = fmaxf(M, s_m2[grp][i]);
    float L = 0.f;
#pragma unroll
    for (int i = 0; i < 4; ++i) L += s_l2[grp][i] * __expf(s_m2[grp][i] - M);

    // partial ctx -> smem (8 warps x 4 KB = 32 KB, reuses stage memory)
    float sc = __expf(m - M);
    float* cs = es + (size_t)w * 1024;
#pragma unroll
    for (int i = 0; i < 32; ++i) cs[i * 32 + lane] = ctx[i] * sc;
    __syncthreads();

    const int gtid = tid & 127;            // 128 threads per group
    uint32_t* ubuf = d_u16[s & 3];
    const float* pc = es + (size_t)grp * 4096;
    for (int wI = gtid; wI < 512; wI += 128) {
        float s0 = 0.f, s1 = 0.f;
#pragma unroll
        for (int p = 0; p < 4; ++p) {
            s0 += pc[(size_t)p * 1024 + 2 * wI];
            s1 += pc[(size_t)p * 1024 + 2 * wI + 1];
        }
        ubuf[(size_t)b * 1024 + kperm(wI)] = packf16(s0 / L, s1 / L);
        ubuf[(size_t)b * 1024 + kperm(512 + wI)] = packf16(hb[2 * wI], hb[2 * wI + 1]);
    }
    {
        float p = __expf(s_sc[grp][gtid] - M) / L;
        out[(size_t)BB * TT * OO + (size_t)b * TT * SS + (size_t)s * SS + gtid] = p;
    }
}

// ---------------- kernels -----------------------------------------------------
__global__ void __launch_bounds__(256) k_convert(const float* __restrict__ st,
                                                 const float* __restrict__ Wih,
                                                 const float* __restrict__ Whh,
                                                 const float* __restrict__ Wfc) {
    int g = blockIdx.x * 256 + threadIdx.x;
    int stride = gridDim.x * 256;
    float4 z = make_float4(0.f, 0.f, 0.f, 0.f);
    for (int i = g; i < BB * HH / 4; i += stride)
        ((float4*)d_c)[i] = z;
    for (int i = g; i < BB * 512 / 4; i += stride)
        ((uint4*)d_h16[3])[i] = make_uint4(0, 0, 0, 0);
    for (int i = g; i < G4 * 512; i += stride) {
        int n = i >> 9;
        int w = i & 511;
        d_Whh16[(size_t)n * 512 + kperm(w)] = packf16(Whh[(size_t)n * HH + 2 * w],
                                                      Whh[(size_t)n * HH + 2 * w + 1]);
    }
    for (int i = g; i < G4 * 128; i += stride) {
        int n = i >> 7;
        int w = i & 127;
        d_Wih16[n * 128 + kperm(w)] = packf16(Wih[(size_t)n * II + 2 * w],
                                              Wih[(size_t)n * II + 2 * w + 1]);
    }
    for (int i = g; i < OO * 1024; i += stride) {
        int n = i >> 10;
        int w = i & 1023;
        d_Wfc16[n * 1024 + kperm(w)] = packf16(Wfc[(size_t)n * 2 * HH + 2 * w],
                                               Wfc[(size_t)n * 2 * HH + 2 * w + 1]);
    }
    for (int i = g; i < 8192 * 128; i += stride) {
        int m = i >> 7;
        int w = i & 127;
        int t_ = m >> 8;
        int b_ = m & 255;
        uint32_t v = 0;
        if (t_ != 0) {
            const float* s = st + (size_t)b_ * TT * II + (size_t)t_ * II + 2 * w;
            v = packf16(s[0], s[1]);
        }
        d_st16[(size_t)m * 128 + kperm(w)] = v;
    }
}

__global__ void __launch_bounds__(256, 2) k_pre(const float* __restrict__ bih,
                                                const float* __restrict__ bhh) {
    extern __shared__ char dyn[];
    gemm_pre(blockIdx.x >> 5, blockIdx.x & 31, bih, bhh, d_Xg16, dyn);
}

// kA: bids laid out [gates nG][attn nA][fc nP][red nR].
// Even t: attn2 covers steps t-1 AND t-2 in one CTA per batch (enc read once).
// Odd t: fc covers steps t-2, t-3; red covers steps t-4, t-5.
__global__ void __launch_bounds__(256, 2) kA(int t, int nG, int nA, int nP,
                                             const float* __restrict__ enc,
                                             const float* __restrict__ bfc,
                                             float* __restrict__ out) {
    extern __shared__ char dyn[];
    __shared__ float s_sc[2][SS];
    __shared__ float s_m2[2][4], s_l2[2][4];
    int bid = blockIdx.x;

    if (bid < nG) {
        gatescell_dev(bid >> 5, bid & 31,
                      d_h16[(t + 3) & 3], d_Xg16 + (size_t)t * BB * 2048,
                      d_h[t & 3], d_h16[t & 3], dyn);
    } else if (bid < nG + nA) {
        int b = bid - nG;              // 0..255, one batch per CTA, two steps
        attn2_dev(b, t, enc, out, dyn, s_sc, s_m2, s_l2);
    } else if (bid < nG + nA + nP) {
        int idx = bid - nG - nA;       // 0..63
        int s = t - 2 - (idx >> 5);    // steps t-2, t-3
        int sub = idx & 31;
        int ks = sub & 3;
        int ctan = (sub >> 2) & 3;
        int ctam = sub >> 4;
        fcpart_dev(ctam, ctan, ks, d_u16[s & 3], d_fcp[s & 3][ks]);
    } else {
        int idx = bid - nG - nA - nP;  // 0..15
        int s = t - 4 - (idx >> 3);    // steps t-4, t-5
        int sub = idx & 7;
        const float* p0 = d_fcp[s & 3][0];
        const float* p1 = d_fcp[s & 3][1];
        const float* p2 = d_fcp[s & 3][2];
        const float* p3 = d_fcp[s & 3][3];
        for (int e = sub * 256 + threadIdx.x; e < BB * OO; e += 8 * 256) {
            int b = e >> 8;
            int o = e & 255;
            float v = p0[e] + p1[e] + p2[e] + p3[e] + bfc[o];
            out[(size_t)b * TT * OO + (size_t)s * OO + o] = v;
        }
    }
}

// ---------------- launch --------------------------------------------------------
extern "C" void kernel_launch(void* const* d_in, const int* in_sizes, int n_in,
                              void* d_out, int out_size) {
    const float* st  = (const float*)d_in[0];
    const float* enc = (const float*)d_in[1];
    const float* Wih = (const float*)d_in[2];
    const float* Whh = (const float*)d_in[3];
    const float* bih = (const float*)d_in[4];
    const float* bhh = (const float*)d_in[5];
    const float* Wfc = (const float*)d_in[6];
    const float* bfc = (const float*)d_in[7];
    float* out = (float*)d_out;

    static const int DYN_PRE = 81920;
    static const int DYN_KA = 98304;   // gates 92160 / attn2 49152 / fc 92160
    cudaFuncSetAttribute(k_pre, cudaFuncAttributeMaxDynamicSharedMemorySize, DYN_PRE);
    cudaFuncSetAttribute(kA, cudaFuncAttributeMaxDynamicSharedMemorySize, DYN_KA);

    k_convert<<<592, 256>>>(st, Wih, Whh, Wfc);
    k_pre<<<2048, 256, DYN_PRE>>>(bih, bhh);

    for (int t = 0; t <= TT + 3; ++t) {
        bool even = (t & 1) == 0;
        int nG = (t < TT) ? 128 : 0;
        int nA = (even && t >= 2 && t <= TT) ? 256 : 0;            // steps t-1,t-2 fused
        int nP = (!even && t >= 3 && t <= TT + 1) ? 64 : 0;        // steps t-2,t-3
        int nR = (!even && t >= 5 && t <= TT + 3) ? 16 : 0;        // steps t-4,t-5
        int total = nG + nA + nP + nR;
        if (total == 0) continue;
        kA<<<total, 256, DYN_KA>>>(t, nG, nA, nP, enc, bfc, out);
    }
}

// round 16
// speedup vs baseline: 1.0163x; 1.0163x over previous
#include <cuda_runtime.h>
#include <cuda_fp16.h>
#include <math.h>
#include <stdint.h>

#define BB 256
#define TT 32
#define SS 128
#define II 256
#define HH 1024
#define OO 256
#define G4 4096

// ---------------- scratch (static device globals; no allocation) ------------
__device__ uint32_t d_Xg16[(size_t)TT * BB * 2048]; // input gates + biases, fp16 pairs
__device__ float d_h[4][BB * HH];                // ring-buffered hidden (fp32)
__device__ uint32_t d_h16[4][BB * 512];          // hidden, f16x2 words, frag-permuted
__device__ float d_c[BB * HH];
__device__ uint32_t d_u16[4][BB * 1024];         // [ctx|h] f16x2 words, permuted
__device__ float d_fcp[4][4][BB * OO];           // split-K FC partials
__device__ uint32_t d_Wih16[G4 * 128];           // fp16 pairs, word-permuted
__device__ uint32_t d_Whh16[(size_t)G4 * 512];
__device__ uint32_t d_Wfc16[OO * 1024];
__device__ uint32_t d_st16[8192 * 128];          // shifted_target fp16, m-major (t*256+b)

// ---------------- helpers ----------------------------------------------------
__device__ __forceinline__ uint32_t packf16(float a, float b) {
    __half2 h = __floats2half2_rn(a, b);
    return *reinterpret_cast<uint32_t*>(&h);
}
__device__ __forceinline__ uint32_t cvta_s(const void* p) {
    return (uint32_t)__cvta_generic_to_shared(p);
}
__device__ __forceinline__ int kperm(int k) {
    return (k & ~7) + ((k & 3) << 1) + ((k >> 2) & 1);
}
#define CPASYNC16(sa, g) asm volatile("cp.async.cg.shared.global [%0], [%1], 16;" :: "r"(sa), "l"(g))
#define CPCOMMIT() asm volatile("cp.async.commit_group;")
#define CPWAIT(n) asm volatile("cp.async.wait_group %0;" :: "n"(n))

__device__ __forceinline__ void mma_f16(float c[4], const uint32_t a[4], const uint32_t b[2]) {
    asm volatile(
        "mma.sync.aligned.m16n8k16.row.col.f32.f16.f16.f32 "
        "{%0,%1,%2,%3}, {%4,%5,%6,%7}, {%8,%9}, {%0,%1,%2,%3};"
        : "+f"(c[0]), "+f"(c[1]), "+f"(c[2]), "+f"(c[3])
        : "r"(a[0]), "r"(a[1]), "r"(a[2]), "r"(a[3]), "r"(b[0]), "r"(b[1]));
}

#define SIG(x) (1.f / (1.f + __expf(-(x))))

// ========== precompute GEMM (k_pre): 128x128 tiles, fp16, depth-2 ============
__device__ __forceinline__ void gemm_pre(
    int ctam, int ctan,
    const float* __restrict__ e1, const float* __restrict__ e2,
    uint32_t* __restrict__ XgO, char* dyn)
{
    uint32_t* As = (uint32_t*)dyn;
    uint32_t* Bs = (uint32_t*)(dyn + 40960);
    const int tid = threadIdx.x;
    const int lane = tid & 31;
    const int wid = tid >> 5;
    const int wm = wid & 3;
    const int wn = wid >> 2;
    const int tg = lane & 3;
    const int gpr = lane >> 2;

    float acc[2][8][4];
#pragma unroll
    for (int i = 0; i < 2; ++i)
#pragma unroll
        for (int j = 0; j < 8; ++j)
#pragma unroll
            for (int k = 0; k < 4; ++k) acc[i][j][k] = 0.f;

    auto stage = [&](int buf, int kcw) {
#pragma unroll
        for (int it = 0; it < 4; ++it) {
            int slot = it * 256 + tid;
            int row = slot >> 3;
            int cc = (slot & 7) << 2;
            CPASYNC16(cvta_s(As + buf * 5120 + row * 40 + cc),
                      d_st16 + (size_t)(ctam * 128 + row) * 128 + kcw + cc);
        }
#pragma unroll
        for (int it = 0; it < 4; ++it) {
            int slot = it * 256 + tid;
            int row = slot >> 3;
            int cc = (slot & 7) << 2;
            CPASYNC16(cvta_s(Bs + buf * 5120 + row * 40 + cc),
                      d_Wih16 + (size_t)(ctan * 128 + row) * 128 + kcw + cc);
        }
    };

    stage(0, 0);
    CPCOMMIT();
    const int nc = 4;
    for (int c = 0; c < nc; ++c) {
        if (c + 1 < nc) { stage((c + 1) & 1, (c + 1) * 32); CPCOMMIT(); CPWAIT(1); }
        else CPWAIT(0);
        __syncthreads();
        const uint32_t* Af = As + (c & 1) * 5120;
        const uint32_t* Bf = Bs + (c & 1) * 5120;
#pragma unroll
        for (int ks = 0; ks < 4; ++ks) {
            uint32_t a[2][4], b[8][2];
#pragma unroll
            for (int mt = 0; mt < 2; ++mt) {
                int r = wm * 32 + mt * 16 + gpr;
                uint2 lo = *(const uint2*)(Af + r * 40 + ks * 8 + tg * 2);
                uint2 hi = *(const uint2*)(Af + (r + 8) * 40 + ks * 8 + tg * 2);
                a[mt][0] = lo.x; a[mt][2] = lo.y;
                a[mt][1] = hi.x; a[mt][3] = hi.y;
            }
#pragma unroll
            for (int nt = 0; nt < 8; ++nt) {
                int n = wn * 64 + nt * 8 + gpr;
                uint2 v = *(const uint2*)(Bf + n * 40 + ks * 8 + tg * 2);
                b[nt][0] = v.x; b[nt][1] = v.y;
            }
#pragma unroll
            for (int mt = 0; mt < 2; ++mt)
#pragma unroll
                for (int nt = 0; nt < 8; ++nt)
                    mma_f16(acc[mt][nt], a[mt], b[nt]);
        }
        __syncthreads();
    }
#pragma unroll
    for (int mt = 0; mt < 2; ++mt)
#pragma unroll
        for (int nt = 0; nt < 8; ++nt) {
            int gm0 = ctam * 128 + wm * 32 + mt * 16 + gpr;
            int gn = ctan * 128 + wn * 64 + nt * 8 + tg * 2;
#pragma unroll
            for (int half = 0; half < 2; ++half) {
                int gm = gm0 + half * 8;
                float v0 = acc[mt][nt][half * 2 + 0] + e1[gn] + e2[gn];
                float v1 = acc[mt][nt][half * 2 + 1] + e1[gn + 1] + e2[gn + 1];
                XgO[(size_t)gm * 2048 + (gn >> 1)] = packf16(v0, v1);
            }
        }
}

// ========== fused gates GEMM + LSTM cell (fp16 fragments) =====================
// 128 CTAs = ctam(4) x ctan(32). CTA 64M x 128N (4 gates x 32 cols).
__device__ __forceinline__ void gatescell_dev(
    int ctam, int ctan,
    const uint32_t* __restrict__ hA,   // h_{t-1}, f16x2 permuted
    const uint32_t* __restrict__ Xg16, // d_Xg16 + t*BB*2048
    float* __restrict__ hOut,
    uint32_t* __restrict__ hOut16,
    char* dyn)
{
    uint32_t* As = (uint32_t*)dyn;
    uint32_t* Bs = (uint32_t*)(dyn + 30720);
    const int tid = threadIdx.x;
    const int lane = tid & 31;
    const int wid = tid >> 5;
    const int wm = wid & 1;
    const int g = wid >> 1;
    const int tg = lane & 3;
    const int gpr = lane >> 2;
    const int q0 = ctan * 32;
    const int m0 = ctam * 64;

    float acc[2][4][4];
#pragma unroll
    for (int i = 0; i < 2; ++i)
#pragma unroll
        for (int j = 0; j < 4; ++j)
#pragma unroll
            for (int k = 0; k < 4; ++k) acc[i][j][k] = 0.f;

    auto stage = [&](int buf, int kcw) {
#pragma unroll
        for (int it = 0; it < 2; ++it) {
            int slot = it * 256 + tid;
            int row = slot >> 3;
            int cc = (slot & 7) << 2;
            CPASYNC16(cvta_s(As + buf * 2560 + row * 40 + cc),
                      hA + (size_t)(m0 + row) * 512 + kcw + cc);
        }
#pragma unroll
        for (int it = 0; it < 4; ++it) {
            int slot = it * 256 + tid;
            int row = slot >> 3;
            int cc = (slot & 7) << 2;
            int wr = (row >> 5) * HH + q0 + (row & 31);
            CPASYNC16(cvta_s(Bs + buf * 5120 + row * 40 + cc),
                      d_Whh16 + (size_t)wr * 512 + kcw + cc);
        }
    };

    stage(0, 0); CPCOMMIT();
    stage(1, 32); CPCOMMIT();
    const int nc = 16;
    for (int c = 0; c < nc; ++c) {
        if (c + 2 < nc) { stage((c + 2) % 3, (c + 2) * 32); CPCOMMIT(); CPWAIT(2); }
        else if (c + 1 < nc) { CPWAIT(1); }
        else { CPWAIT(0); }
        __syncthreads();
        const uint32_t* Af = As + (c % 3) * 2560;
        const uint32_t* Bf = Bs + (c % 3) * 5120;
#pragma unroll
        for (int ks = 0; ks < 4; ++ks) {
            uint32_t a[2][4], b[4][2];
#pragma unroll
            for (int mt = 0; mt < 2; ++mt) {
                int r = wm * 32 + mt * 16 + gpr;
                uint2 lo = *(const uint2*)(Af + r * 40 + ks * 8 + tg * 2);
                uint2 hi = *(const uint2*)(Af + (r + 8) * 40 + ks * 8 + tg * 2);
                a[mt][0] = lo.x; a[mt][2] = lo.y;
                a[mt][1] = hi.x; a[mt][3] = hi.y;
            }
#pragma unroll
            for (int nt = 0; nt < 4; ++nt) {
                int n = g * 32 + nt * 8 + gpr;
                uint2 v = *(const uint2*)(Bf + n * 40 + ks * 8 + tg * 2);
                b[nt][0] = v.x; b[nt][1] = v.y;
            }
#pragma unroll
            for (int mt = 0; mt < 2; ++mt)
#pragma unroll
                for (int nt = 0; nt < 4; ++nt)
                    mma_f16(acc[mt][nt], a[mt], b[nt]);
        }
        __syncthreads();
    }

    // gate exchange: ep[row 64][n 128], stride 132
    float* ep = (float*)dyn;
    __syncthreads();
#pragma unroll
    for (int mt = 0; mt < 2; ++mt)
#pragma unroll
        for (int nt = 0; nt < 4; ++nt) {
            int r0 = wm * 32 + mt * 16 + gpr;
            int col = g * 32 + nt * 8 + tg * 2;
            *(float2*)(ep + r0 * 132 + col) = make_float2(acc[mt][nt][0], acc[mt][nt][1]);
            *(float2*)(ep + (r0 + 8) * 132 + col) = make_float2(acc[mt][nt][2], acc[mt][nt][3]);
        }
    __syncthreads();

#pragma unroll
    for (int k = 0; k < 4; ++k) {
        int idx = k * 256 + tid;
        int row = idx >> 4;
        int wq = idx & 15;
        int b = m0 + row;
        int q = q0 + wq * 2;
        const uint32_t* Xw = Xg16 + (size_t)b * 2048 + (q >> 1);
        float2 xi = __half22float2(*(const __half2*)&Xw[0]);
        float2 xf = __half22float2(*(const __half2*)&Xw[512]);
        float2 xg = __half22float2(*(const __half2*)&Xw[1024]);
        float2 xo = __half22float2(*(const __half2*)&Xw[1536]);
        int qq = wq * 2;
        float2 ei = *(const float2*)(ep + row * 132 + qq);
        float2 ef = *(const float2*)(ep + row * 132 + 32 + qq);
        float2 eg = *(const float2*)(ep + row * 132 + 64 + qq);
        float2 eo = *(const float2*)(ep + row * 132 + 96 + qq);
        size_t hb = (size_t)b * HH + q;
        float2 c2 = *(const float2*)(d_c + hb);
        c2.x = SIG(ef.x + xf.x) * c2.x + SIG(ei.x + xi.x) * tanhf(eg.x + xg.x);
        c2.y = SIG(ef.y + xf.y) * c2.y + SIG(ei.y + xi.y) * tanhf(eg.y + xg.y);
        float h0 = SIG(eo.x + xo.x) * tanhf(c2.x);
        float h1 = SIG(eo.y + xo.y) * tanhf(c2.y);
        *(float2*)(d_c + hb) = c2;
        *(float2*)(hOut + hb) = make_float2(h0, h1);
        hOut16[(size_t)b * 512 + kperm((q0 >> 1) + wq)] = packf16(h0, h1);
    }
}

// ========== FC split-K partial GEMM (fp16) ====================================
__device__ __forceinline__ void fcpart_dev(
    int ctam, int ctan, int kslice,
    const uint32_t* __restrict__ u16, float* __restrict__ part)
{
    extern __shared__ char dyn[];
    uint32_t* Af = (uint32_t*)dyn;
    uint32_t* Bf = (uint32_t*)(dyn + 61440);
    const int tid = threadIdx.x;
    const int lane = tid & 31;
    const int wid = tid >> 5;
    const int wm = wid & 3;
    const int wn = wid >> 2;
    const int tg = lane & 3;
    const int gpr = lane >> 2;
    const int k0w = kslice * 256;

    float acc[2][4][4];
#pragma unroll
    for (int i = 0; i < 2; ++i)
#pragma unroll
        for (int j = 0; j < 4; ++j)
#pragma unroll
            for (int k = 0; k < 4; ++k) acc[i][j][k] = 0.f;

    auto stage = [&](int buf, int kcw) {
#pragma unroll
        for (int it = 0; it < 4; ++it) {
            int slot = it * 256 + tid;
            int row = slot >> 3;
            int cc = (slot & 7) << 2;
            CPASYNC16(cvta_s(Af + buf * 5120 + row * 40 + cc),
                      u16 + (size_t)(ctam * 128 + row) * 1024 + k0w + kcw + cc);
        }
#pragma unroll
        for (int it = 0; it < 2; ++it) {
            int slot = it * 256 + tid;
            int row = slot >> 3;
            int cc = (slot & 7) << 2;
            CPASYNC16(cvta_s(Bf + buf * 2560 + row * 40 + cc),
                      d_Wfc16 + (size_t)(ctan * 64 + row) * 1024 + k0w + kcw + cc);
        }
    };

    stage(0, 0); CPCOMMIT();
    stage(1, 32); CPCOMMIT();
    const int nc = 8;
    for (int c = 0; c < nc; ++c) {
        if (c + 2 < nc) { stage((c + 2) % 3, (c + 2) * 32); CPCOMMIT(); CPWAIT(2); }
        else if (c + 1 < nc) { CPWAIT(1); }
        else { CPWAIT(0); }
        __syncthreads();
        const uint32_t* A = Af + (c % 3) * 5120;
        const uint32_t* B = Bf + (c % 3) * 2560;
#pragma unroll
        for (int ks = 0; ks < 4; ++ks) {
            uint32_t a[2][4], b[4][2];
#pragma unroll
            for (int mt = 0; mt < 2; ++mt) {
                int r = wm * 32 + mt * 16 + gpr;
                uint2 lo = *(const uint2*)(A + r * 40 + ks * 8 + tg * 2);
                uint2 hi = *(const uint2*)(A + (r + 8) * 40 + ks * 8 + tg * 2);
                a[mt][0] = lo.x; a[mt][2] = lo.y;
                a[mt][1] = hi.x; a[mt][3] = hi.y;
            }
#pragma unroll
            for (int nt = 0; nt < 4; ++nt) {
                int n = wn * 32 + nt * 8 + gpr;
                uint2 v = *(const uint2*)(B + n * 40 + ks * 8 + tg * 2);
                b[nt][0] = v.x; b[nt][1] = v.y;
            }
#pragma unroll
            for (int mt = 0; mt < 2; ++mt)
#pragma unroll
                for (int nt = 0; nt < 4; ++nt)
                    mma_f16(acc[mt][nt], a[mt], b[nt]);
        }
        __syncthreads();
    }
#pragma unroll
    for (int mt = 0; mt < 2; ++mt)
#pragma unroll
        for (int nt = 0; nt < 4; ++nt) {
            int gm0 = ctam * 128 + wm * 32 + mt * 16 + gpr;
            int gn = ctan * 64 + wn * 32 + nt * 8 + tg * 2;
            *(float2*)(part + (size_t)gm0 * OO + gn) =
                make_float2(acc[mt][nt][0], acc[mt][nt][1]);
            *(float2*)(part + (size_t)(gm0 + 8) * OO + gn) =
                make_float2(acc[mt][nt][2], acc[mt][nt][3]);
        }
}

// ========== attention (fp32, cp.async pipelined, er register-cached) ==========
// One call = one batch. 8 warps; warp w scans rows w*16+j with a per-warp
// 3-stage smem ring. enc row values cached in registers for dot+ctx reuse.
__device__ __forceinline__ void attn_dev(int b, int tatt, const float* __restrict__ enc,
                                         const float* __restrict__ hcur,
                                         float* __restrict__ out, int uslot, char* dyn,
                                         float* s_scores, float* s_m, float* s_l)
{
    float* es = (float*)dyn;
    const int tid = threadIdx.x;
    const int lane = tid & 31;
    const int w = tid >> 5;

    const float* hb = hcur + (size_t)b * HH;
    float hreg[32];
#pragma unroll
    for (int i = 0; i < 32; ++i) hreg[i] = hb[i * 32 + lane];

    const float* encb = enc + (size_t)b * SS * HH;
#pragma unroll
    for (int p = 0; p < 3; ++p) {
        const float* gsrc = encb + (size_t)(w * 16 + p) * HH;
        float* sbuf = es + ((size_t)(p % 3) * 8 + w) * 1024;
#pragma unroll
        for (int q = 0; q < 8; ++q)
            CPASYNC16(cvta_s(sbuf + q * 128 + lane * 4), gsrc + q * 128 + lane * 4);
        CPCOMMIT();
    }

    float m = -1e30f, l = 0.f;
    float ctx[32];
#pragma unroll
    for (int i = 0; i < 32; ++i) ctx[i] = 0.f;

    for (int j = 0; j < 16; ++j) {
        if (j < 14) { CPWAIT(2); }
        else if (j == 14) { CPWAIT(1); }
        else { CPWAIT(0); }
        __syncwarp();
        const float* e = es + ((size_t)(j % 3) * 8 + w) * 1024;
        float er[32];
        float dot = 0.f;
#pragma unroll
        for (int i = 0; i < 32; ++i) {
            er[i] = e[i * 32 + lane];
            dot += hreg[i] * er[i];
        }
#pragma unroll
        for (int o = 16; o; o >>= 1) dot += __shfl_xor_sync(0xffffffffu, dot, o);
        if (lane == 0) s_scores[w * 16 + j] = dot;

        float nm = fmaxf(m, dot);
        float al = __expf(m - nm);
        float p = __expf(dot - nm);
        l = l * al + p;
#pragma unroll
        for (int i = 0; i < 32; ++i) ctx[i] = ctx[i] * al + p * er[i];
        m = nm;
        __syncwarp();
        if (j + 3 < 16) {
            const float* gsrc = encb + (size_t)(w * 16 + j + 3) * HH;
            float* sbuf = es + ((size_t)(j % 3) * 8 + w) * 1024;
#pragma unroll
            for (int q = 0; q < 8; ++q)
                CPASYNC16(cvta_s(sbuf + q * 128 + lane * 4), gsrc + q * 128 + lane * 4);
            CPCOMMIT();
        }
    }
    if (lane == 0) { s_m[w] = m; s_l[w] = l; }
    __syncthreads();

    float M = -1e30f;
#pragma unroll
    for (int i = 0; i < 8; ++i) M = fmaxf(M, s_m[i]);
    float L = 0.f;
#pragma unroll
    for (int i = 0; i < 8; ++i) L += s_l[i] * __expf(s_m[i] - M);

    float sc = __expf(m - M);
    float* cs = es + (size_t)w * 1024;
#pragma unroll
    for (int i = 0; i < 32; ++i) cs[i * 32 + lane] = ctx[i] * sc;
    __syncthreads();

    uint32_t* ubuf = d_u16[uslot];
    for (int wI = tid; wI < 512; wI += 256) {
        float s0 = 0.f, s1 = 0.f;
#pragma unroll
        for (int ww = 0; ww < 8; ++ww) {
            s0 += es[(size_t)ww * 1024 + 2 * wI];
            s1 += es[(size_t)ww * 1024 + 2 * wI + 1];
        }
        ubuf[(size_t)b * 1024 + kperm(wI)] = packf16(s0 / L, s1 / L);
        ubuf[(size_t)b * 1024 + kperm(512 + wI)] = packf16(hb[2 * wI], hb[2 * wI + 1]);
    }
    if (tid < SS) {
        float p = __expf(s_scores[tid] - M) / L;
        out[(size_t)BB * TT * OO + (size_t)b * TT * SS + (size_t)tatt * SS + tid] = p;
    }
}

// ---------------- kernels -----------------------------------------------------
__global__ void __launch_bounds__(256) k_convert(const float* __restrict__ st,
                                                 const float* __restrict__ Wih,
                                                 const float* __restrict__ Whh,
                                                 const float* __restrict__ Wfc) {
    int g = blockIdx.x * 256 + threadIdx.x;
    int stride = gridDim.x * 256;
    float4 z = make_float4(0.f, 0.f, 0.f, 0.f);
    for (int i = g; i < BB * HH / 4; i += stride)
        ((float4*)d_c)[i] = z;
    for (int i = g; i < BB * 512 / 4; i += stride)
        ((uint4*)d_h16[3])[i] = make_uint4(0, 0, 0, 0);
    for (int i = g; i < G4 * 512; i += stride) {
        int n = i >> 9;
        int w = i & 511;
        d_Whh16[(size_t)n * 512 + kperm(w)] = packf16(Whh[(size_t)n * HH + 2 * w],
                                                      Whh[(size_t)n * HH + 2 * w + 1]);
    }
    for (int i = g; i < G4 * 128; i += stride) {
        int n = i >> 7;
        int w = i & 127;
        d_Wih16[n * 128 + kperm(w)] = packf16(Wih[(size_t)n * II + 2 * w],
                                              Wih[(size_t)n * II + 2 * w + 1]);
    }
    for (int i = g; i < OO * 1024; i += stride) {
        int n = i >> 10;
        int w = i & 1023;
        d_Wfc16[n * 1024 + kperm(w)] = packf16(Wfc[(size_t)n * 2 * HH + 2 * w],
                                               Wfc[(size_t)n * 2 * HH + 2 * w + 1]);
    }
    for (int i = g; i < 8192 * 128; i += stride) {
        int m = i >> 7;
        int w = i & 127;
        int t_ = m >> 8;
        int b_ = m & 255;
        uint32_t v = 0;
        if (t_ != 0) {
            const float* s = st + (size_t)b_ * TT * II + (size_t)t_ * II + 2 * w;
            v = packf16(s[0], s[1]);
        }
        d_st16[(size_t)m * 128 + kperm(w)] = v;
    }
}

__global__ void __launch_bounds__(256, 2) k_pre(const float* __restrict__ bih,
                                                const float* __restrict__ bhh) {
    extern __shared__ char dyn[];
    gemm_pre(blockIdx.x >> 5, blockIdx.x & 31, bih, bhh, d_Xg16, dyn);
}

// kA: every step. bid order [gates 128][attn 128 (2 batches each)][fc 32][red 16]
// so gates and attention co-reside in wave 1 (304 CTAs ~ 1.03 waves at 2/SM).
__global__ void __launch_bounds__(256, 2) kA(int t, int nG, int nA, int nP,
                                             const float* __restrict__ enc,
                                             const float* __restrict__ bfc,
                                             float* __restrict__ out) {
    extern __shared__ char dyn[];
    __shared__ float s_scores[SS];
    __shared__ float s_m[8], s_l[8];
    int bid = blockIdx.x;

    if (bid < nG) {
        gatescell_dev(bid >> 5, bid & 31,
                      d_h16[(t + 3) & 3], d_Xg16 + (size_t)t * BB * 2048,
                      d_h[t & 3], d_h16[t & 3], dyn);
    } else if (bid < nG + nA) {
        // attention for step t-1: 2 batches per CTA
        int ta = t - 1;
        int b0 = (bid - nG) * 2;
#pragma unroll
        for (int sub = 0; sub < 2; ++sub) {
            attn_dev(b0 + sub, ta, enc, d_h[ta & 3], out, ta & 3, dyn,
                     s_scores, s_m, s_l);
            __syncthreads();
        }
    } else if (bid < nG + nA + nP) {
        int idx = bid - nG - nA;       // 0..31
        int tfc = t - 2;
        int ks = idx & 3;
        int ctan = (idx >> 2) & 3;
        int ctam = idx >> 4;
        fcpart_dev(ctam, ctan, ks, d_u16[tfc & 3], d_fcp[tfc & 3][ks]);
    } else {
        int idx = bid - nG - nA - nP;  // 0..15
        int tr = t - 3;
        const float* p0 = d_fcp[tr & 3][0];
        const float* p1 = d_fcp[tr & 3][1];
        const float* p2 = d_fcp[tr & 3][2];
        const float* p3 = d_fcp[tr & 3][3];
        for (int e = idx * 256 + threadIdx.x; e < BB * OO; e += 16 * 256) {
            int b = e >> 8;
            int o = e & 255;
            float v = p0[e] + p1[e] + p2[e] + p3[e] + bfc[o];
            out[(size_t)b * TT * OO + (size_t)tr * OO + o] = v;
        }
    }
}

// ---------------- launch --------------------------------------------------------
extern "C" void kernel_launch(void* const* d_in, const int* in_sizes, int n_in,
                              void* d_out, int out_size) {
    const float* st  = (const float*)d_in[0];
    const float* enc = (const float*)d_in[1];
    const float* Wih = (const float*)d_in[2];
    const float* Whh = (const float*)d_in[3];
    const float* bih = (const float*)d_in[4];
    const float* bhh = (const float*)d_in[5];
    const float* Wfc = (const float*)d_in[6];
    const float* bfc = (const float*)d_in[7];
    float* out = (float*)d_out;

    static const int DYN_PRE = 81920;
    static const int DYN_KA = 98304;   // gates 92160 / attn 98304 / fc 92160
    cudaFuncSetAttribute(k_pre, cudaFuncAttributeMaxDynamicSharedMemorySize, DYN_PRE);
    cudaFuncSetAttribute(kA, cudaFuncAttributeMaxDynamicSharedMemorySize, DYN_KA);

    k_convert<<<592, 256>>>(st, Wih, Whh, Wfc);
    k_pre<<<2048, 256, DYN_PRE>>>(bih, bhh);

    for (int t = 0; t <= TT + 2; ++t) {
        int nG = (t < TT) ? 128 : 0;                     // gates+cell step t
        int nA = (t >= 1 && t <= TT) ? 128 : 0;          // attention step t-1 (2/CTA)
        int nP = (t >= 2 && t <= TT + 1) ? 32 : 0;       // fc partials step t-2
        int nR = (t >= 3) ? 16 : 0;                      // fc reduce step t-3
        kA<<<nG + nA + nP + nR, 256, DYN_KA>>>(t, nG, nA, nP, enc, bfc, out);
    }
}